// round 10
// baseline (speedup 1.0000x reference)
#include <cuda_runtime.h>

// Problem constants: VOCAB=128, EMB=256, NUM_CHARS=257, BATCH=8, Lm1=256
#define LM1          256
#define EMB_N        256
#define ROWS         257               // output rows per batch (start + 256)
#define BATCH_N      8
#define ROWS_PER_BLK 2
#define THREADS      (32 * BATCH_N * ROWS_PER_BLK)   // 512
#define GRID         ((ROWS + ROWS_PER_BLK - 1) / ROWS_PER_BLK)  // 129: one wave

__global__ void __launch_bounds__(THREADS)
encoder_final(const int*   __restrict__ tokens,     // (8, 257) int32
              const float* __restrict__ emb,        // (128, 256)
              const float* __restrict__ dwk,        // (256, 1, 3, 3)
              const float* __restrict__ dwb,        // (256,)
              const float* __restrict__ dw,         // (256, 1)
              const float* __restrict__ db,         // (1,)
              const float* __restrict__ sv,         // (1, 256)
              float*       __restrict__ out)        // (8, 257, 256)
{
    const int lane = threadIdx.x & 31;
    const int warp = threadIdx.x >> 5;           // 0..15
    const int b    = warp & 7;                   // batch index
    const int r    = blockIdx.x * ROWS_PER_BLK + (warp >> 3);  // warp-uniform row
    if (r >= ROWS) return;
    float* orow = out + ((size_t)b * ROWS + r) * EMB_N;

    if (r == 0) {                                // warp-uniform
        const float4 s0 = reinterpret_cast<const float4*>(sv)[2 * lane];
        const float4 s1 = reinterpret_cast<const float4*>(sv)[2 * lane + 1];
        reinterpret_cast<float4*>(orow)[2 * lane]     = s0;
        reinterpret_cast<float4*>(orow)[2 * lane + 1] = s1;
        return;
    }
    const int c = r - 1;

    // ---- start the dependent chain immediately
    const int tok = tokens[b * ROWS + c];        // tokens[:, :-1][b, c]
    const float* xrow = emb + tok * EMB_N;
    const float4 x0v = reinterpret_cast<const float4*>(xrow)[2 * lane];
    const float4 x1v = reinterpret_cast<const float4*>(xrow)[2 * lane + 1];

    // ---- row-uniform scalars (independent loads, issue while gather in flight)
    float k[9];
    #pragma unroll
    for (int i = 0; i < 9; i++) k[i] = dwk[c * 9 + i];
    const float bias = dwb[c];
    const float dw0_ = dw[0];
    const float dwc  = dw[c];
    const float dwc1 = (c + 1 < LM1) ? dw[c + 1] : 0.f;
    const float db0  = db[0];

    // ---- P = sum_{w=1}^{c-1} dw[w]; S = total; tail T derived by subtraction
    const float4 d0 = reinterpret_cast<const float4*>(dw)[2 * lane];
    const float4 d1 = reinterpret_cast<const float4*>(dw)[2 * lane + 1];
    const float dv[8] = {d0.x, d0.y, d0.z, d0.w, d1.x, d1.y, d1.z, d1.w};
    float P = 0.f, S = 0.f;
    #pragma unroll
    for (int j = 0; j < 8; j++) {
        const unsigned w = 8 * lane + j;
        S += dv[j];
        if (w - 1u < (unsigned)(c - 1)) P += dv[j];   // 1 <= w <= c-1
    }
    #pragma unroll
    for (int off = 16; off; off >>= 1) {
        P += __shfl_xor_sync(0xffffffffu, P, off);
        S += __shfl_xor_sync(0xffffffffu, S, off);
    }
    const float T = (c == 0) ? (S - dw0_ - dwc1)
                             : (S - P - dw0_ - dwc - dwc1);

    // ---- neighbors via shuffle (no extra LDGs); edges -> 0 == SAME padding
    float xm = __shfl_up_sync(0xffffffffu, x1v.w, 1);   // e = 8*lane - 1
    float xp = __shfl_down_sync(0xffffffffu, x0v.x, 1); // e = 8*lane + 8
    if (lane == 0)  xm = 0.f;
    if (lane == 31) xp = 0.f;

    // ---- per-element evaluation: e = 8*lane + j
    const float xs[10] = {xm, x0v.x, x0v.y, x0v.z, x0v.w,
                              x1v.x, x1v.y, x1v.z, x1v.w, xp};
    const float rb   = fmaxf(bias, 0.f);
    const float base = fmaf(rb, T, db0);
    float res[8];
    #pragma unroll
    for (int j = 0; j < 8; j++) {
        const float a0 = xs[j], a1 = xs[j + 1], a2 = xs[j + 2];
        // conv columns by W-offset: A = -1 (k[0],k[3],k[6]); B = 0; C = +1
        const float A  = fmaf(k[0], a0, fmaf(k[3], a1, k[6] * a2));
        const float B  = fmaf(k[1], a0, fmaf(k[4], a1, k[7] * a2));
        const float C  = fmaf(k[2], a0, fmaf(k[5], a1, k[8] * a2));
        const float AB = A + B;
        const float r_wc1 = fmaxf(A + bias, 0.f);               // w == c+1
        float acc;
        if (c == 0) {
            acc = fmaf(dw0_, fmaxf(B + bias, 0.f), fmaf(dwc1, r_wc1, base));
        } else {
            const float r_w0  = fmaxf(B + C + bias, 0.f);       // w == 0
            const float r_mid = fmaxf(AB + C + bias, 0.f);      // 1 <= w <= c-1
            const float r_wc  = fmaxf(AB + bias, 0.f);          // w == c
            acc = fmaf(dw0_, r_w0,
                  fmaf(P,    r_mid,
                  fmaf(dwc,  r_wc,
                  fmaf(dwc1, r_wc1, base))));
        }
        res[j] = fmaxf(acc, 0.f);
    }
    reinterpret_cast<float4*>(orow)[2 * lane]     = make_float4(res[0], res[1], res[2], res[3]);
    reinterpret_cast<float4*>(orow)[2 * lane + 1] = make_float4(res[4], res[5], res[6], res[7]);
}

extern "C" void kernel_launch(void* const* d_in, const int* in_sizes, int n_in,
                              void* d_out, int out_size) {
    const int*   tokens    = (const int*)  d_in[0];
    const float* emb       = (const float*)d_in[1];
    const float* dw_kernel = (const float*)d_in[2];
    const float* dw_bias   = (const float*)d_in[3];
    const float* dense_w   = (const float*)d_in[4];
    const float* dense_b   = (const float*)d_in[5];
    const float* start_var = (const float*)d_in[6];
    float* out = (float*)d_out;

    encoder_final<<<GRID, THREADS>>>(tokens, emb, dw_kernel, dw_bias,
                                    dense_w, dense_b, start_var, out);
}

// round 11
// speedup vs baseline: 1.1088x; 1.1088x over previous
#include <cuda_runtime.h>

// Problem constants: VOCAB=128, EMB=256, NUM_CHARS=257, BATCH=8, Lm1=256
#define LM1          256
#define EMB_N        256
#define ROWS         257               // output rows per batch (start + 256)
#define BATCH_N      8
#define ROWS_PER_BLK 2
#define THREADS      (32 * BATCH_N * ROWS_PER_BLK)   // 512
#define GRID         ((ROWS + ROWS_PER_BLK - 1) / ROWS_PER_BLK)  // 129: one wave

__global__ void __launch_bounds__(THREADS)
encoder_final(const int*   __restrict__ tokens,     // (8, 257) int32
              const float* __restrict__ emb,        // (128, 256)
              const float* __restrict__ dwk,        // (256, 1, 3, 3)
              const float* __restrict__ dwb,        // (256,)
              const float* __restrict__ dw,         // (256, 1)
              const float* __restrict__ db,         // (1,)
              const float* __restrict__ sv,         // (1, 256)
              float*       __restrict__ out)        // (8, 257, 256)
{
    const int lane = threadIdx.x & 31;
    const int warp = threadIdx.x >> 5;           // 0..15
    const int b    = warp & 7;                   // batch index
    const int r    = blockIdx.x * ROWS_PER_BLK + (warp >> 3);  // warp-uniform row
    if (r >= ROWS) return;
    float* orow = out + ((size_t)b * ROWS + r) * EMB_N;

    if (r == 0) {                                // warp-uniform
        const float4 s0 = reinterpret_cast<const float4*>(sv)[2 * lane];
        const float4 s1 = reinterpret_cast<const float4*>(sv)[2 * lane + 1];
        reinterpret_cast<float4*>(orow)[2 * lane]     = s0;
        reinterpret_cast<float4*>(orow)[2 * lane + 1] = s1;
        return;
    }
    const int c = r - 1;

    // ---- start the dependent chain immediately
    const int tok = tokens[b * ROWS + c];        // tokens[:, :-1][b, c]
    const float* xrow = emb + tok * EMB_N;
    const float4 x0v = reinterpret_cast<const float4*>(xrow)[2 * lane];
    const float4 x1v = reinterpret_cast<const float4*>(xrow)[2 * lane + 1];

    // ---- row-uniform scalars (independent loads, issue while gather in flight)
    float k[9];
    #pragma unroll
    for (int i = 0; i < 9; i++) k[i] = dwk[c * 9 + i];
    const float bias = dwb[c];
    const float dw0_ = dw[0];
    const float dwc  = dw[c];
    const float dwc1 = (c + 1 < LM1) ? dw[c + 1] : 0.f;
    const float db0  = db[0];

    // ---- P = sum_{w=1}^{c-1} dw[w]; S = total; tail T derived by subtraction
    const float4 d0 = reinterpret_cast<const float4*>(dw)[2 * lane];
    const float4 d1 = reinterpret_cast<const float4*>(dw)[2 * lane + 1];
    const float dv[8] = {d0.x, d0.y, d0.z, d0.w, d1.x, d1.y, d1.z, d1.w};
    float P = 0.f, S = 0.f;
    #pragma unroll
    for (int j = 0; j < 8; j++) {
        const unsigned w = 8 * lane + j;
        S += dv[j];
        if (w - 1u < (unsigned)(c - 1)) P += dv[j];   // 1 <= w <= c-1
    }
    #pragma unroll
    for (int off = 16; off; off >>= 1) {
        P += __shfl_xor_sync(0xffffffffu, P, off);
        S += __shfl_xor_sync(0xffffffffu, S, off);
    }
    const float T = (c == 0) ? (S - dw0_ - dwc1)
                             : (S - P - dw0_ - dwc - dwc1);

    // ---- neighbors via shuffle (no extra LDGs); edges -> 0 == SAME padding
    float xm = __shfl_up_sync(0xffffffffu, x1v.w, 1);   // e = 8*lane - 1
    float xp = __shfl_down_sync(0xffffffffu, x0v.x, 1); // e = 8*lane + 8
    if (lane == 0)  xm = 0.f;
    if (lane == 31) xp = 0.f;

    // ---- per-element evaluation: e = 8*lane + j
    const float xs[10] = {xm, x0v.x, x0v.y, x0v.z, x0v.w,
                              x1v.x, x1v.y, x1v.z, x1v.w, xp};
    const float rb   = fmaxf(bias, 0.f);
    const float base = fmaf(rb, T, db0);
    float res[8];
    #pragma unroll
    for (int j = 0; j < 8; j++) {
        const float a0 = xs[j], a1 = xs[j + 1], a2 = xs[j + 2];
        // conv columns by W-offset: A = -1 (k[0],k[3],k[6]); B = 0; C = +1
        const float A  = fmaf(k[0], a0, fmaf(k[3], a1, k[6] * a2));
        const float B  = fmaf(k[1], a0, fmaf(k[4], a1, k[7] * a2));
        const float C  = fmaf(k[2], a0, fmaf(k[5], a1, k[8] * a2));
        const float AB = A + B;
        const float r_wc1 = fmaxf(A + bias, 0.f);               // w == c+1
        float acc;
        if (c == 0) {
            acc = fmaf(dw0_, fmaxf(B + bias, 0.f), fmaf(dwc1, r_wc1, base));
        } else {
            const float r_w0  = fmaxf(B + C + bias, 0.f);       // w == 0
            const float r_mid = fmaxf(AB + C + bias, 0.f);      // 1 <= w <= c-1
            const float r_wc  = fmaxf(AB + bias, 0.f);          // w == c
            acc = fmaf(dw0_, r_w0,
                  fmaf(P,    r_mid,
                  fmaf(dwc,  r_wc,
                  fmaf(dwc1, r_wc1, base))));
        }
        res[j] = fmaxf(acc, 0.f);
    }
    reinterpret_cast<float4*>(orow)[2 * lane]     = make_float4(res[0], res[1], res[2], res[3]);
    reinterpret_cast<float4*>(orow)[2 * lane + 1] = make_float4(res[4], res[5], res[6], res[7]);
}

extern "C" void kernel_launch(void* const* d_in, const int* in_sizes, int n_in,
                              void* d_out, int out_size) {
    const int*   tokens    = (const int*)  d_in[0];
    const float* emb       = (const float*)d_in[1];
    const float* dw_kernel = (const float*)d_in[2];
    const float* dw_bias   = (const float*)d_in[3];
    const float* dense_w   = (const float*)d_in[4];
    const float* dense_b   = (const float*)d_in[5];
    const float* start_var = (const float*)d_in[6];
    float* out = (float*)d_out;

    encoder_final<<<GRID, THREADS>>>(tokens, emb, dw_kernel, dw_bias,
                                    dense_w, dense_b, start_var, out);
}